// round 14
// baseline (speedup 1.0000x reference)
#include <cuda_runtime.h>
#include <cuda_bf16.h>
#include <cstdint>

// Problem constants
#define BB 4
#define HH 16
#define LL 8192
#define DD 64
#define BH (BB*HH)            // 64
#define NPOS (BH*LL)          // 524288

#define TS 128                // positions per block (M tile)
#define RSB 256               // bf16 row stride bytes (128 k-vals); XOR-swizzled
#define NCTA (NPOS / TS)      // 4096

// Scratch (no cudaMalloc allowed)
__device__ float g_w[NPOS];
__device__ float g_psum[NCTA];        // per-CTA partial sums (4096)
__device__ float g_rsum[BH];

__device__ __forceinline__ float tanh_mufu(float x) {
    float r;
    asm("tanh.approx.f32 %0, %1;" : "=f"(r) : "f"(x));
    return r;
}

__device__ __forceinline__ uint32_t pack_bf16(float lo, float hi) {
    uint32_t r;
    asm("cvt.rn.bf16x2.f32 %0, %1, %2;" : "=r"(r) : "f"(hi), "f"(lo));
    return r;
}

#define LDSM_X4(r, addr) \
    asm volatile("ldmatrix.sync.aligned.m8n8.x4.shared.b16 {%0,%1,%2,%3}, [%4];" \
        : "=r"((r)[0]), "=r"((r)[1]), "=r"((r)[2]), "=r"((r)[3]) : "r"(addr))

#define MMA_BF16(c, a, b0_, b1_) \
    asm volatile( \
        "mma.sync.aligned.m16n8k16.row.col.f32.bf16.bf16.f32 " \
        "{%0,%1,%2,%3}, {%4,%5,%6,%7}, {%8,%9}, {%0,%1,%2,%3};" \
        : "+f"((c)[0]), "+f"((c)[1]), "+f"((c)[2]), "+f"((c)[3]) \
        : "r"((a)[0]), "r"((a)[1]), "r"((a)[2]), "r"((a)[3]), \
          "r"(b0_), "r"(b1_))

// Dynamic smem layout (bytes from base)
#define SM_X    0                        // TS*128 bf16 = 32768
#define SM_W    (TS * 256)               // 32768; 64*128 bf16 = 16384
#define SM_BIAS (SM_W + DD * 256)        // 49152
#define SM_VA   (SM_BIAS + 256)
#define SM_RED  (SM_VA + 256)
#define SM_TOT  (SM_RED + 32)

// ---------------------------------------------------------------------------
// Kernel 1: bf16 mma.sync GEMM [128 pos x 64 dims, K=128] + fused epilogue.
// 128 threads / 4 warps; warp-tile 32 pos x 64 dims; 4 CTAs/SM for DRAM
// duty-cycle overlap. Block-wide coalesced staging, XOR swizzle, MUFU tanh.
// ---------------------------------------------------------------------------
__global__ __launch_bounds__(128, 4) void attn_logits_kernel(
    const float* __restrict__ q, const float* __restrict__ k,
    const int* __restrict__ mask,
    const float* __restrict__ Wa_w, const float* __restrict__ Wa_b,
    const float* __restrict__ Ua_w, const float* __restrict__ Ua_b,
    const float* __restrict__ va_w, const float* __restrict__ va_b)
{
    extern __shared__ char smem[];
    __nv_bfloat16* Xs  = (__nv_bfloat16*)(smem + SM_X);
    __nv_bfloat16* Wsm = (__nv_bfloat16*)(smem + SM_W);
    float* bias = (float*)(smem + SM_BIAS);
    float* vas  = (float*)(smem + SM_VA);
    float* red  = (float*)(smem + SM_RED);

    const int t    = threadIdx.x;      // 0..127
    const int lane = t & 31;
    const int w    = t >> 5;           // 0..3
    const int gid  = lane >> 2;        // 0..7
    const int tig  = lane & 3;         // 0..3
    const int pos0 = blockIdx.x * TS;
    const int m0   = w * 32;           // warp's 32-pos row base

    const uint32_t sbX = (uint32_t)__cvta_generic_to_shared(Xs);
    const uint32_t sbW = (uint32_t)__cvta_generic_to_shared(Wsm);

    if (t < 64) {
        bias[t] = Wa_b[t] + Ua_b[t];
        vas[t]  = va_w[t];
    }

    // ---- stage X (q -> chunks 0..7, k -> chunks 8..15), linear copy ----
    #pragma unroll
    for (int it = 0; it < 8; it++) {
        const int idx8 = t + it * 128;            // 0..1023
        const int pos = idx8 >> 3, c = idx8 & 7;
        const float4* s4 = (const float4*)(q + (size_t)(pos0 + pos) * DD) + 2 * c;
        float4 a = s4[0], b = s4[1];
        uint4 u;
        u.x = pack_bf16(a.x, a.y); u.y = pack_bf16(a.z, a.w);
        u.z = pack_bf16(b.x, b.y); u.w = pack_bf16(b.z, b.w);
        const int ch = c ^ (pos & 7);
        *(uint4*)((char*)Xs + pos * RSB + ch * 16) = u;
    }
    #pragma unroll
    for (int it = 0; it < 8; it++) {
        const int idx8 = t + it * 128;
        const int pos = idx8 >> 3, c = idx8 & 7;
        const float4* s4 = (const float4*)(k + (size_t)(pos0 + pos) * DD) + 2 * c;
        float4 a = s4[0], b = s4[1];
        uint4 u;
        u.x = pack_bf16(a.x, a.y); u.y = pack_bf16(a.z, a.w);
        u.z = pack_bf16(b.x, b.y); u.w = pack_bf16(b.z, b.w);
        const int ch = (8 + c) ^ (pos & 7);
        *(uint4*)((char*)Xs + pos * RSB + ch * 16) = u;
    }
    // ---- stage W (Wa -> chunks 0..7, Ua -> 8..15) ----
    #pragma unroll
    for (int it = 0; it < 4; it++) {
        const int idx8 = t + it * 128;            // 0..511
        const int pos = idx8 >> 3, c = idx8 & 7;
        const float4* s4 = (const float4*)(Wa_w + (size_t)pos * DD) + 2 * c;
        float4 a = s4[0], b = s4[1];
        uint4 u;
        u.x = pack_bf16(a.x, a.y); u.y = pack_bf16(a.z, a.w);
        u.z = pack_bf16(b.x, b.y); u.w = pack_bf16(b.z, b.w);
        const int ch = c ^ (pos & 7);
        *(uint4*)((char*)Wsm + pos * RSB + ch * 16) = u;
    }
    #pragma unroll
    for (int it = 0; it < 4; it++) {
        const int idx8 = t + it * 128;
        const int pos = idx8 >> 3, c = idx8 & 7;
        const float4* s4 = (const float4*)(Ua_w + (size_t)pos * DD) + 2 * c;
        float4 a = s4[0], b = s4[1];
        uint4 u;
        u.x = pack_bf16(a.x, a.y); u.y = pack_bf16(a.z, a.w);
        u.z = pack_bf16(b.x, b.y); u.w = pack_bf16(b.z, b.w);
        const int ch = (8 + c) ^ (pos & 7);
        *(uint4*)((char*)Wsm + pos * RSB + ch * 16) = u;
    }
    __syncthreads();

    float acc[2][8][4];
    #pragma unroll
    for (int mt = 0; mt < 2; mt++)
        #pragma unroll
        for (int nt = 0; nt < 8; nt++)
            #pragma unroll
            for (int j = 0; j < 4; j++) acc[mt][nt][j] = 0.f;

    // ldmatrix lane bases (swizzle applied per k-step)
    const int rowA = m0 + (lane & 15);
    const uint32_t baseA = sbX + (uint32_t)rowA * RSB;
    const int swA = rowA & 7;
    const int ckA0 = lane >> 4;                    // 0/1
    const int rowB = ((lane >> 4) << 3) + (lane & 7);
    const uint32_t baseB = sbW + (uint32_t)rowB * RSB;
    const int ckB0 = (lane >> 3) & 1;              // 0/1

    #pragma unroll
    for (int ks = 0; ks < 8; ks++) {               // K=128, k16 per MMA
        uint32_t af[2][4];
        LDSM_X4(af[0], baseA + (uint32_t)(((2 * ks + ckA0) ^ swA) << 4));
        LDSM_X4(af[1], baseA + 16u * RSB
                     + (uint32_t)(((2 * ks + ckA0) ^ ((rowA + 16) & 7)) << 4));
        uint32_t bf[4][4];
        #pragma unroll
        for (int np = 0; np < 4; np++)
            LDSM_X4(bf[np], baseB + (uint32_t)(np * 16 * RSB)
                          + (uint32_t)(((2 * ks + ckB0) ^ ((rowB + np * 16) & 7)) << 4));
        #pragma unroll
        for (int mt = 0; mt < 2; mt++)
            #pragma unroll
            for (int np = 0; np < 4; np++) {
                MMA_BF16(acc[mt][2 * np],     af[mt], bf[np][0], bf[np][1]);
                MMA_BF16(acc[mt][2 * np + 1], af[mt], bf[np][2], bf[np][3]);
            }
    }

    // ---- epilogue: tanh (MUFU), va-dot, 4-lane reduce, masked exp, sum(w) ----
    const float vb = va_b[0];
    float wsum = 0.f;
    #pragma unroll
    for (int mt = 0; mt < 2; mt++) {
        float s0 = 0.f, s1 = 0.f;
        #pragma unroll
        for (int nt = 0; nt < 8; nt++) {
            const int c0 = nt * 8 + 2 * tig;
            const float vv0 = vas[c0], vv1 = vas[c0 + 1];
            const float bb0 = bias[c0], bb1 = bias[c0 + 1];
            s0 += vv0 * tanh_mufu(acc[mt][nt][0] + bb0)
                + vv1 * tanh_mufu(acc[mt][nt][1] + bb1);
            s1 += vv0 * tanh_mufu(acc[mt][nt][2] + bb0)
                + vv1 * tanh_mufu(acc[mt][nt][3] + bb1);
        }
        s0 += __shfl_xor_sync(0xffffffffu, s0, 1, 4);
        s0 += __shfl_xor_sync(0xffffffffu, s0, 2, 4);
        s1 += __shfl_xor_sync(0xffffffffu, s1, 1, 4);
        s1 += __shfl_xor_sync(0xffffffffu, s1, 2, 4);
        if (tig == 0) {
            int p0 = pos0 + m0 + mt * 16 + gid;
            float w0 = (mask[p0] != 0) ? __expf(s0 + vb) : 0.f;
            g_w[p0] = w0;
            int p1 = p0 + 8;
            float w1 = (mask[p1] != 0) ? __expf(s1 + vb) : 0.f;
            g_w[p1] = w1;
            wsum += w0 + w1;
        }
    }
    #pragma unroll
    for (int m = 16; m >= 1; m >>= 1)
        wsum += __shfl_xor_sync(0xffffffffu, wsum, m);
    if (lane == 0) red[w] = wsum;
    __syncthreads();
    if (t == 0)
        g_psum[blockIdx.x] = (red[0] + red[1]) + (red[2] + red[3]);
}

// ---------------------------------------------------------------------------
// Kernel 2: per-(b,h) reciprocal of sum of 64 CTA partials. Deterministic.
// ---------------------------------------------------------------------------
__global__ __launch_bounds__(32) void row_sum_kernel()
{
    const int bh = blockIdx.x;
    const int l  = threadIdx.x;
    float s = g_psum[bh * 64 + l] + g_psum[bh * 64 + 32 + l];
    #pragma unroll
    for (int m = 16; m >= 1; m >>= 1)
        s += __shfl_xor_sync(0xffffffffu, s, m);
    if (l == 0) g_rsum[bh] = 1.f / s;
}

// ---------------------------------------------------------------------------
// Kernel 3: out = alpha * v  (float4)
// ---------------------------------------------------------------------------
__global__ __launch_bounds__(1024) void scale_v_kernel(
    const float* __restrict__ v, float* __restrict__ out)
{
    int i4 = blockIdx.x * 1024 + threadIdx.x;   // 8192 blocks * 1024 = N/4
    int pos = i4 >> 4;                           // 16 float4 per position
    int bh  = pos >> 13;                         // / 8192
    float w = g_w[pos] * g_rsum[bh];
    float4 vv = ((const float4*)v)[i4];
    vv.x *= w; vv.y *= w; vv.z *= w; vv.w *= w;
    ((float4*)out)[i4] = vv;
}

extern "C" void kernel_launch(void* const* d_in, const int* in_sizes, int n_in,
                              void* d_out, int out_size)
{
    const float* q    = (const float*)d_in[0];
    const float* k    = (const float*)d_in[1];
    const float* v    = (const float*)d_in[2];
    const int*   mask = (const int*)d_in[3];
    const float* Wa_w = (const float*)d_in[4];
    const float* Wa_b = (const float*)d_in[5];
    const float* Ua_w = (const float*)d_in[6];
    const float* Ua_b = (const float*)d_in[7];
    const float* va_w = (const float*)d_in[8];
    const float* va_b = (const float*)d_in[9];
    float* out = (float*)d_out;

    cudaFuncSetAttribute(attn_logits_kernel,
                         cudaFuncAttributeMaxDynamicSharedMemorySize, SM_TOT);

    attn_logits_kernel<<<NCTA, 128, SM_TOT>>>(q, k, mask, Wa_w, Wa_b,
                                              Ua_w, Ua_b, va_w, va_b);
    row_sum_kernel<<<BH, 32>>>();
    scale_v_kernel<<<(NPOS * DD / 4) / 1024, 1024>>>(v, out);
}

// round 15
// speedup vs baseline: 1.1317x; 1.1317x over previous
#include <cuda_runtime.h>
#include <cuda_bf16.h>
#include <cstdint>

// Problem constants
#define BB 4
#define HH 16
#define LL 8192
#define DD 64
#define BH (BB*HH)            // 64
#define NPOS (BH*LL)          // 524288

#define TS 256                // positions per block (M tile)
#define RSB 256               // bf16 row stride bytes (128 k-vals); XOR-swizzled
#define NCTA (NPOS / TS)      // 2048
#define CPB (NCTA / BH)       // 32 CTAs per (b,h) row

// Scratch (no cudaMalloc allowed)
__device__ float g_w[NPOS];
__device__ float g_psum[NCTA];        // per-CTA partial sums
__device__ float g_rsum[BH];
__device__ unsigned int g_cnt = 0;    // completion counter (reset by last CTA)

__device__ __forceinline__ float tanh_mufu(float x) {
    float r;
    asm("tanh.approx.f32 %0, %1;" : "=f"(r) : "f"(x));
    return r;
}

__device__ __forceinline__ uint32_t pack_bf16(float lo, float hi) {
    uint32_t r;
    asm("cvt.rn.bf16x2.f32 %0, %1, %2;" : "=r"(r) : "f"(hi), "f"(lo));
    return r;
}

__device__ __forceinline__ void stg_cs(float* p, float v) {
    asm volatile("st.global.cs.f32 [%0], %1;" :: "l"(p), "f"(v) : "memory");
}

#define LDSM_X4(r, addr) \
    asm volatile("ldmatrix.sync.aligned.m8n8.x4.shared.b16 {%0,%1,%2,%3}, [%4];" \
        : "=r"((r)[0]), "=r"((r)[1]), "=r"((r)[2]), "=r"((r)[3]) : "r"(addr))

#define MMA_BF16(c, a, b0_, b1_) \
    asm volatile( \
        "mma.sync.aligned.m16n8k16.row.col.f32.bf16.bf16.f32 " \
        "{%0,%1,%2,%3}, {%4,%5,%6,%7}, {%8,%9}, {%0,%1,%2,%3};" \
        : "+f"((c)[0]), "+f"((c)[1]), "+f"((c)[2]), "+f"((c)[3]) \
        : "r"((a)[0]), "r"((a)[1]), "r"((a)[2]), "r"((a)[3]), \
          "r"(b0_), "r"(b1_))

// ---------------------------------------------------------------------------
// Kernel 1: bf16 mma.sync GEMM [256 pos x 64 dims, K=128 single phase]
//   e = va . tanh(Wa q + Ua k + b); w = mask ? exp(e) : 0; + per-CTA sum(w)
// Last CTA to finish reduces all partials -> g_rsum (replaces kernel2).
// ---------------------------------------------------------------------------
__global__ __launch_bounds__(256, 2) void attn_logits_kernel(
    const float* __restrict__ q, const float* __restrict__ k,
    const int* __restrict__ mask,
    const float* __restrict__ Wa_w, const float* __restrict__ Wa_b,
    const float* __restrict__ Ua_w, const float* __restrict__ Ua_b,
    const float* __restrict__ va_w, const float* __restrict__ va_b)
{
    __shared__ alignas(16) __nv_bfloat16 Xs[TS * 128];   // [256 pos][128 k] swz
    __shared__ alignas(16) __nv_bfloat16 Wsm[DD * 128];  // [64 n][128 k] swz
    __shared__ float bias[DD];
    __shared__ float vas[DD];
    __shared__ float red[8];
    __shared__ unsigned int s_rank;

    const int t    = threadIdx.x;      // 0..255
    const int lane = t & 31;
    const int w    = t >> 5;           // 0..7
    const int gid  = lane >> 2;        // 0..7
    const int tig  = lane & 3;         // 0..3
    const int pos0 = blockIdx.x * TS;
    const int m0   = w * 32;           // warp's 32-pos row base

    const uint32_t sbX = (uint32_t)__cvta_generic_to_shared(Xs);
    const uint32_t sbW = (uint32_t)__cvta_generic_to_shared(Wsm);

    if (t < 64) {
        bias[t] = Wa_b[t] + Ua_b[t];
        vas[t]  = va_w[t];
    }

    // ---- stage X (q -> chunks 0..7, k -> chunks 8..15), linear copy ----
    #pragma unroll
    for (int it = 0; it < 8; it++) {
        const int idx8 = t + it * 256;            // 0..2047
        const int pos = idx8 >> 3, c = idx8 & 7;
        const float4* s4 = (const float4*)(q + (size_t)(pos0 + pos) * DD) + 2 * c;
        float4 a = s4[0], b = s4[1];
        uint4 u;
        u.x = pack_bf16(a.x, a.y); u.y = pack_bf16(a.z, a.w);
        u.z = pack_bf16(b.x, b.y); u.w = pack_bf16(b.z, b.w);
        const int ch = c ^ (pos & 7);
        *(uint4*)((char*)Xs + pos * RSB + ch * 16) = u;
    }
    #pragma unroll
    for (int it = 0; it < 8; it++) {
        const int idx8 = t + it * 256;
        const int pos = idx8 >> 3, c = idx8 & 7;
        const float4* s4 = (const float4*)(k + (size_t)(pos0 + pos) * DD) + 2 * c;
        float4 a = s4[0], b = s4[1];
        uint4 u;
        u.x = pack_bf16(a.x, a.y); u.y = pack_bf16(a.z, a.w);
        u.z = pack_bf16(b.x, b.y); u.w = pack_bf16(b.z, b.w);
        const int ch = (8 + c) ^ (pos & 7);
        *(uint4*)((char*)Xs + pos * RSB + ch * 16) = u;
    }
    // ---- stage W (Wa -> chunks 0..7, Ua -> 8..15) ----
    #pragma unroll
    for (int it = 0; it < 2; it++) {
        const int idx8 = t + it * 256;            // 0..511
        const int pos = idx8 >> 3, c = idx8 & 7;
        const float4* s4 = (const float4*)(Wa_w + (size_t)pos * DD) + 2 * c;
        float4 a = s4[0], b = s4[1];
        uint4 u;
        u.x = pack_bf16(a.x, a.y); u.y = pack_bf16(a.z, a.w);
        u.z = pack_bf16(b.x, b.y); u.w = pack_bf16(b.z, b.w);
        const int ch = c ^ (pos & 7);
        *(uint4*)((char*)Wsm + pos * RSB + ch * 16) = u;
    }
    #pragma unroll
    for (int it = 0; it < 2; it++) {
        const int idx8 = t + it * 256;
        const int pos = idx8 >> 3, c = idx8 & 7;
        const float4* s4 = (const float4*)(Ua_w + (size_t)pos * DD) + 2 * c;
        float4 a = s4[0], b = s4[1];
        uint4 u;
        u.x = pack_bf16(a.x, a.y); u.y = pack_bf16(a.z, a.w);
        u.z = pack_bf16(b.x, b.y); u.w = pack_bf16(b.z, b.w);
        const int ch = (8 + c) ^ (pos & 7);
        *(uint4*)((char*)Wsm + pos * RSB + ch * 16) = u;
    }
    __syncthreads();

    float acc[2][8][4];
    #pragma unroll
    for (int mt = 0; mt < 2; mt++)
        #pragma unroll
        for (int nt = 0; nt < 8; nt++)
            #pragma unroll
            for (int j = 0; j < 4; j++) acc[mt][nt][j] = 0.f;

    // ldmatrix lane bases (swizzle applied per k-step)
    const int rowA = m0 + (lane & 15);
    const uint32_t baseA = sbX + (uint32_t)rowA * RSB;
    const int swA = rowA & 7;
    const int ckA0 = lane >> 4;                    // 0/1
    const int rowB = ((lane >> 4) << 3) + (lane & 7);
    const uint32_t baseB = sbW + (uint32_t)rowB * RSB;
    const int ckB0 = (lane >> 3) & 1;              // 0/1

    #pragma unroll
    for (int ks = 0; ks < 8; ks++) {               // K=128, k16 per MMA
        uint32_t af[2][4];
        LDSM_X4(af[0], baseA + (uint32_t)(((2 * ks + ckA0) ^ swA) << 4));
        LDSM_X4(af[1], baseA + 16u * RSB
                     + (uint32_t)(((2 * ks + ckA0) ^ ((rowA + 16) & 7)) << 4));
        uint32_t bf[4][4];
        #pragma unroll
        for (int np = 0; np < 4; np++)
            LDSM_X4(bf[np], baseB + (uint32_t)(np * 16 * RSB)
                          + (uint32_t)(((2 * ks + ckB0) ^ ((rowB + np * 16) & 7)) << 4));
        #pragma unroll
        for (int mt = 0; mt < 2; mt++)
            #pragma unroll
            for (int np = 0; np < 4; np++) {
                MMA_BF16(acc[mt][2 * np],     af[mt], bf[np][0], bf[np][1]);
                MMA_BF16(acc[mt][2 * np + 1], af[mt], bf[np][2], bf[np][3]);
            }
    }

    // ---- epilogue: tanh (MUFU), va-dot, 4-lane reduce, masked exp, sum(w) ----
    const float vb = va_b[0];
    float wsum = 0.f;
    #pragma unroll
    for (int mt = 0; mt < 2; mt++) {
        float s0 = 0.f, s1 = 0.f;
        #pragma unroll
        for (int nt = 0; nt < 8; nt++) {
            const int c0 = nt * 8 + 2 * tig;
            const float vv0 = vas[c0], vv1 = vas[c0 + 1];
            const float bb0 = bias[c0], bb1 = bias[c0 + 1];
            s0 += vv0 * tanh_mufu(acc[mt][nt][0] + bb0)
                + vv1 * tanh_mufu(acc[mt][nt][1] + bb1);
            s1 += vv0 * tanh_mufu(acc[mt][nt][2] + bb0)
                + vv1 * tanh_mufu(acc[mt][nt][3] + bb1);
        }
        s0 += __shfl_xor_sync(0xffffffffu, s0, 1, 4);
        s0 += __shfl_xor_sync(0xffffffffu, s0, 2, 4);
        s1 += __shfl_xor_sync(0xffffffffu, s1, 1, 4);
        s1 += __shfl_xor_sync(0xffffffffu, s1, 2, 4);
        if (tig == 0) {
            int p0 = pos0 + m0 + mt * 16 + gid;
            float w0 = (mask[p0] != 0) ? __expf(s0 + vb) : 0.f;
            stg_cs(&g_w[p0], w0);
            int p1 = p0 + 8;
            float w1 = (mask[p1] != 0) ? __expf(s1 + vb) : 0.f;
            stg_cs(&g_w[p1], w1);
            wsum += w0 + w1;
        }
    }
    #pragma unroll
    for (int m = 16; m >= 1; m >>= 1)
        wsum += __shfl_xor_sync(0xffffffffu, wsum, m);
    if (lane == 0) red[w] = wsum;
    __syncthreads();
    if (t == 0) {
        float s = (red[0] + red[1]) + (red[2] + red[3])
                + (red[4] + red[5]) + (red[6] + red[7]);
        g_psum[blockIdx.x] = s;
        __threadfence();
        s_rank = atomicAdd(&g_cnt, 1u);
    }
    __syncthreads();

    // ---- last CTA reduces partials -> g_rsum (replaces kernel2) ----
    if (s_rank == NCTA - 1) {
        __threadfence();   // all g_psum writes visible
        if (t < BH) {      // 64 threads, one (b,h) each; fixed-order sum
            const float* p = g_psum + t * CPB;
            float s = 0.f;
            #pragma unroll
            for (int i = 0; i < CPB; i++) s += p[i];
            g_rsum[t] = 1.f / s;
        }
        if (t == 0) g_cnt = 0;   // reset for next graph replay
    }
}

// ---------------------------------------------------------------------------
// Kernel 2: out = alpha * v  (float4, ILP=2)
// ---------------------------------------------------------------------------
__global__ __launch_bounds__(1024) void scale_v_kernel(
    const float* __restrict__ v, float* __restrict__ out)
{
    const int base = blockIdx.x * 2048 + threadIdx.x;
    #pragma unroll
    for (int j = 0; j < 2; j++) {
        const int i4 = base + j * 1024;
        const int pos = i4 >> 4;                 // 16 float4 per position
        const int bh  = pos >> 13;               // / 8192
        float w = g_w[pos] * g_rsum[bh];
        float4 vv = ((const float4*)v)[i4];
        vv.x *= w; vv.y *= w; vv.z *= w; vv.w *= w;
        ((float4*)out)[i4] = vv;
    }
}

extern "C" void kernel_launch(void* const* d_in, const int* in_sizes, int n_in,
                              void* d_out, int out_size)
{
    const float* q    = (const float*)d_in[0];
    const float* k    = (const float*)d_in[1];
    const float* v    = (const float*)d_in[2];
    const int*   mask = (const int*)d_in[3];
    const float* Wa_w = (const float*)d_in[4];
    const float* Wa_b = (const float*)d_in[5];
    const float* Ua_w = (const float*)d_in[6];
    const float* Ua_b = (const float*)d_in[7];
    const float* va_w = (const float*)d_in[8];
    const float* va_b = (const float*)d_in[9];
    float* out = (float*)d_out;

    attn_logits_kernel<<<NCTA, 256>>>(q, k, mask, Wa_w, Wa_b,
                                      Ua_w, Ua_b, va_w, va_b);
    scale_v_kernel<<<(NPOS * DD / 4) / 2048, 1024>>>(v, out);
}

// round 16
// speedup vs baseline: 1.2272x; 1.0844x over previous
#include <cuda_runtime.h>
#include <cuda_bf16.h>
#include <cstdint>

// Problem constants
#define BB 4
#define HH 16
#define LL 8192
#define DD 64
#define BH (BB*HH)            // 64
#define NPOS (BH*LL)          // 524288

#define TS 256                // positions per block (M tile)
#define RSB 256               // bf16 row stride bytes (128 k-vals); XOR-swizzled
#define NCTA (NPOS / TS)      // 2048

// Scratch (no cudaMalloc allowed)
__device__ float g_w[NPOS];
__device__ float g_psum[NCTA];        // per-CTA partial sums (2048)
__device__ float g_rsum[BH];

__device__ __forceinline__ float tanh_mufu(float x) {
    float r;
    asm("tanh.approx.f32 %0, %1;" : "=f"(r) : "f"(x));
    return r;
}

__device__ __forceinline__ uint32_t pack_bf16(float lo, float hi) {
    uint32_t r;
    asm("cvt.rn.bf16x2.f32 %0, %1, %2;" : "=r"(r) : "f"(hi), "f"(lo));
    return r;
}

#define LDSM_X4(r, addr) \
    asm volatile("ldmatrix.sync.aligned.m8n8.x4.shared.b16 {%0,%1,%2,%3}, [%4];" \
        : "=r"((r)[0]), "=r"((r)[1]), "=r"((r)[2]), "=r"((r)[3]) : "r"(addr))

#define MMA_BF16(c, a, b0_, b1_) \
    asm volatile( \
        "mma.sync.aligned.m16n8k16.row.col.f32.bf16.bf16.f32 " \
        "{%0,%1,%2,%3}, {%4,%5,%6,%7}, {%8,%9}, {%0,%1,%2,%3};" \
        : "+f"((c)[0]), "+f"((c)[1]), "+f"((c)[2]), "+f"((c)[3]) \
        : "r"((a)[0]), "r"((a)[1]), "r"((a)[2]), "r"((a)[3]), \
          "r"(b0_), "r"(b1_))

// ---------------------------------------------------------------------------
// Kernel 1: bf16 mma.sync GEMM [256 pos x 64 dims, K=128 single phase]
//   e = va . tanh(Wa q + Ua k + b); w = mask ? exp(e) : 0; + per-CTA sum(w)
// 256 threads / 8 warps; warp-tile 32 pos x 64 dims. Block-wide coalesced
// staging (max MLP), XOR-swizzled smem, MUFU tanh.  (R13-proven shape.)
// ---------------------------------------------------------------------------
__global__ __launch_bounds__(256, 2) void attn_logits_kernel(
    const float* __restrict__ q, const float* __restrict__ k,
    const int* __restrict__ mask,
    const float* __restrict__ Wa_w, const float* __restrict__ Wa_b,
    const float* __restrict__ Ua_w, const float* __restrict__ Ua_b,
    const float* __restrict__ va_w, const float* __restrict__ va_b)
{
    __shared__ alignas(16) __nv_bfloat16 Xs[TS * 128];   // [256 pos][128 k] swz
    __shared__ alignas(16) __nv_bfloat16 Wsm[DD * 128];  // [64 n][128 k] swz
    __shared__ float bias[DD];
    __shared__ float vas[DD];
    __shared__ float red[8];

    const int t    = threadIdx.x;      // 0..255
    const int lane = t & 31;
    const int w    = t >> 5;           // 0..7
    const int gid  = lane >> 2;        // 0..7
    const int tig  = lane & 3;         // 0..3
    const int pos0 = blockIdx.x * TS;
    const int m0   = w * 32;           // warp's 32-pos row base

    const uint32_t sbX = (uint32_t)__cvta_generic_to_shared(Xs);
    const uint32_t sbW = (uint32_t)__cvta_generic_to_shared(Wsm);

    if (t < 64) {
        bias[t] = Wa_b[t] + Ua_b[t];
        vas[t]  = va_w[t];
    }

    // ---- stage X (q -> chunks 0..7, k -> chunks 8..15), linear copy ----
    #pragma unroll
    for (int it = 0; it < 8; it++) {
        const int idx8 = t + it * 256;            // 0..2047
        const int pos = idx8 >> 3, c = idx8 & 7;
        const float4* s4 = (const float4*)(q + (size_t)(pos0 + pos) * DD) + 2 * c;
        float4 a = s4[0], b = s4[1];
        uint4 u;
        u.x = pack_bf16(a.x, a.y); u.y = pack_bf16(a.z, a.w);
        u.z = pack_bf16(b.x, b.y); u.w = pack_bf16(b.z, b.w);
        const int ch = c ^ (pos & 7);
        *(uint4*)((char*)Xs + pos * RSB + ch * 16) = u;
    }
    #pragma unroll
    for (int it = 0; it < 8; it++) {
        const int idx8 = t + it * 256;
        const int pos = idx8 >> 3, c = idx8 & 7;
        const float4* s4 = (const float4*)(k + (size_t)(pos0 + pos) * DD) + 2 * c;
        float4 a = s4[0], b = s4[1];
        uint4 u;
        u.x = pack_bf16(a.x, a.y); u.y = pack_bf16(a.z, a.w);
        u.z = pack_bf16(b.x, b.y); u.w = pack_bf16(b.z, b.w);
        const int ch = (8 + c) ^ (pos & 7);
        *(uint4*)((char*)Xs + pos * RSB + ch * 16) = u;
    }
    // ---- stage W (Wa -> chunks 0..7, Ua -> 8..15) ----
    #pragma unroll
    for (int it = 0; it < 2; it++) {
        const int idx8 = t + it * 256;            // 0..511
        const int pos = idx8 >> 3, c = idx8 & 7;
        const float4* s4 = (const float4*)(Wa_w + (size_t)pos * DD) + 2 * c;
        float4 a = s4[0], b = s4[1];
        uint4 u;
        u.x = pack_bf16(a.x, a.y); u.y = pack_bf16(a.z, a.w);
        u.z = pack_bf16(b.x, b.y); u.w = pack_bf16(b.z, b.w);
        const int ch = c ^ (pos & 7);
        *(uint4*)((char*)Wsm + pos * RSB + ch * 16) = u;
    }
    #pragma unroll
    for (int it = 0; it < 2; it++) {
        const int idx8 = t + it * 256;
        const int pos = idx8 >> 3, c = idx8 & 7;
        const float4* s4 = (const float4*)(Ua_w + (size_t)pos * DD) + 2 * c;
        float4 a = s4[0], b = s4[1];
        uint4 u;
        u.x = pack_bf16(a.x, a.y); u.y = pack_bf16(a.z, a.w);
        u.z = pack_bf16(b.x, b.y); u.w = pack_bf16(b.z, b.w);
        const int ch = (8 + c) ^ (pos & 7);
        *(uint4*)((char*)Wsm + pos * RSB + ch * 16) = u;
    }
    __syncthreads();

    float acc[2][8][4];
    #pragma unroll
    for (int mt = 0; mt < 2; mt++)
        #pragma unroll
        for (int nt = 0; nt < 8; nt++)
            #pragma unroll
            for (int j = 0; j < 4; j++) acc[mt][nt][j] = 0.f;

    // ldmatrix lane bases (swizzle applied per k-step)
    const int rowA = m0 + (lane & 15);
    const uint32_t baseA = sbX + (uint32_t)rowA * RSB;
    const int swA = rowA & 7;
    const int ckA0 = lane >> 4;                    // 0/1
    const int rowB = ((lane >> 4) << 3) + (lane & 7);
    const uint32_t baseB = sbW + (uint32_t)rowB * RSB;
    const int ckB0 = (lane >> 3) & 1;              // 0/1

    #pragma unroll
    for (int ks = 0; ks < 8; ks++) {               // K=128, k16 per MMA
        uint32_t af[2][4];
        LDSM_X4(af[0], baseA + (uint32_t)(((2 * ks + ckA0) ^ swA) << 4));
        LDSM_X4(af[1], baseA + 16u * RSB
                     + (uint32_t)(((2 * ks + ckA0) ^ ((rowA + 16) & 7)) << 4));
        uint32_t bf[4][4];
        #pragma unroll
        for (int np = 0; np < 4; np++)
            LDSM_X4(bf[np], baseB + (uint32_t)(np * 16 * RSB)
                          + (uint32_t)(((2 * ks + ckB0) ^ ((rowB + np * 16) & 7)) << 4));
        #pragma unroll
        for (int mt = 0; mt < 2; mt++)
            #pragma unroll
            for (int np = 0; np < 4; np++) {
                MMA_BF16(acc[mt][2 * np],     af[mt], bf[np][0], bf[np][1]);
                MMA_BF16(acc[mt][2 * np + 1], af[mt], bf[np][2], bf[np][3]);
            }
    }

    // ---- epilogue: tanh (MUFU), va-dot, 4-lane reduce, masked exp, sum(w) ----
    const float vb = va_b[0];
    float wsum = 0.f;
    #pragma unroll
    for (int mt = 0; mt < 2; mt++) {
        float s0 = 0.f, s1 = 0.f;
        #pragma unroll
        for (int nt = 0; nt < 8; nt++) {
            const int c0 = nt * 8 + 2 * tig;
            const float vv0 = vas[c0], vv1 = vas[c0 + 1];
            const float bb0 = bias[c0], bb1 = bias[c0 + 1];
            s0 += vv0 * tanh_mufu(acc[mt][nt][0] + bb0)
                + vv1 * tanh_mufu(acc[mt][nt][1] + bb1);
            s1 += vv0 * tanh_mufu(acc[mt][nt][2] + bb0)
                + vv1 * tanh_mufu(acc[mt][nt][3] + bb1);
        }
        s0 += __shfl_xor_sync(0xffffffffu, s0, 1, 4);
        s0 += __shfl_xor_sync(0xffffffffu, s0, 2, 4);
        s1 += __shfl_xor_sync(0xffffffffu, s1, 1, 4);
        s1 += __shfl_xor_sync(0xffffffffu, s1, 2, 4);
        if (tig == 0) {
            int p0 = pos0 + m0 + mt * 16 + gid;
            float w0 = (mask[p0] != 0) ? __expf(s0 + vb) : 0.f;
            g_w[p0] = w0;
            int p1 = p0 + 8;
            float w1 = (mask[p1] != 0) ? __expf(s1 + vb) : 0.f;
            g_w[p1] = w1;
            wsum += w0 + w1;
        }
    }
    // per-warp total (non-tig0 lanes carry 0), then per-CTA total
    #pragma unroll
    for (int m = 16; m >= 1; m >>= 1)
        wsum += __shfl_xor_sync(0xffffffffu, wsum, m);
    if (lane == 0) red[w] = wsum;
    __syncthreads();
    if (t == 0) {
        float s = (red[0] + red[1]) + (red[2] + red[3])
                + (red[4] + red[5]) + (red[6] + red[7]);
        g_psum[blockIdx.x] = s;
    }
}

// ---------------------------------------------------------------------------
// Kernel 2: per-(b,h) reciprocal of sum of 32 CTA partials. Deterministic.
// ---------------------------------------------------------------------------
__global__ __launch_bounds__(32) void row_sum_kernel()
{
    const int bh = blockIdx.x;
    const int l  = threadIdx.x;
    float s = g_psum[bh * 32 + l];
    #pragma unroll
    for (int m = 16; m >= 1; m >>= 1)
        s += __shfl_xor_sync(0xffffffffu, s, m);
    if (l == 0) g_rsum[bh] = 1.f / s;
}

// ---------------------------------------------------------------------------
// Kernel 3: out = alpha * v  (float4, ILP=2)
// ---------------------------------------------------------------------------
__global__ __launch_bounds__(1024) void scale_v_kernel(
    const float* __restrict__ v, float* __restrict__ out)
{
    const int base = blockIdx.x * 2048 + threadIdx.x;
    #pragma unroll
    for (int j = 0; j < 2; j++) {
        const int i4 = base + j * 1024;
        const int pos = i4 >> 4;                 // 16 float4 per position
        const int bh  = pos >> 13;               // / 8192
        float w = g_w[pos] * g_rsum[bh];
        float4 vv = ((const float4*)v)[i4];
        vv.x *= w; vv.y *= w; vv.z *= w; vv.w *= w;
        ((float4*)out)[i4] = vv;
    }
}

extern "C" void kernel_launch(void* const* d_in, const int* in_sizes, int n_in,
                              void* d_out, int out_size)
{
    const float* q    = (const float*)d_in[0];
    const float* k    = (const float*)d_in[1];
    const float* v    = (const float*)d_in[2];
    const int*   mask = (const int*)d_in[3];
    const float* Wa_w = (const float*)d_in[4];
    const float* Wa_b = (const float*)d_in[5];
    const float* Ua_w = (const float*)d_in[6];
    const float* Ua_b = (const float*)d_in[7];
    const float* va_w = (const float*)d_in[8];
    const float* va_b = (const float*)d_in[9];
    float* out = (float*)d_out;

    attn_logits_kernel<<<NCTA, 256>>>(q, k, mask, Wa_w, Wa_b,
                                      Ua_w, Ua_b, va_w, va_b);
    row_sum_kernel<<<BH, 32>>>();
    scale_v_kernel<<<(NPOS * DD / 4) / 2048, 1024>>>(v, out);
}